// round 1
// baseline (speedup 1.0000x reference)
#include <cuda_runtime.h>
#include <math.h>

#define NN   50000
#define EE   800000
#define DIN  127
#define DD   128
#define NCLS 40
#define EPSV 1e-8f

// Scratch buffers (allocation-free rule: __device__ globals)
__device__ float g_A[NN * DD];
__device__ float g_B[NN * DD];
__device__ float g_S[NN * DD];

__device__ __forceinline__ float warpSum(float v) {
#pragma unroll
    for (int o = 16; o; o >>= 1) v += __shfl_xor_sync(0xffffffffu, v, o);
    return v;
}

// ---------------------------------------------------------------------------
// Stage 1: expmap0. One warp per node.
// ---------------------------------------------------------------------------
__global__ void expmap_kernel(const float* __restrict__ nf, float* __restrict__ out) {
    int lane = threadIdx.x & 31;
    int warp = (blockIdx.x * blockDim.x + threadIdx.x) >> 5;
    if (warp >= NN) return;
    const float* u = nf + (size_t)warp * DIN;
    float v[4];
    float ss = 0.f;
#pragma unroll
    for (int i = 0; i < 4; i++) {
        int j = lane * 4 + i;
        v[i] = (j < DIN) ? u[j] : 0.f;
        ss += v[i] * v[i];
    }
    ss = warpSum(ss);
    float nrm = fmaxf(sqrtf(ss), EPSV);
    float f = sinhf(nrm) / nrm;
    float* o = out + (size_t)warp * DD;
    if (lane == 0) o[0] = coshf(nrm);
#pragma unroll
    for (int i = 0; i < 4; i++) {
        int j = lane * 4 + i;
        if (j < DIN) o[1 + j] = f * v[i];
    }
}

// ---------------------------------------------------------------------------
// Stage 2/4: H = X @ W^T + b, then Lorentz time/scale epilogue per row.
// BM=128, BN=128 (full width -> block owns complete rows), BK=16, 8x8 microtile.
// ---------------------------------------------------------------------------
__global__ __launch_bounds__(256) void gemm_lorentz(
    const float* __restrict__ X, const float* __restrict__ W,
    const float* __restrict__ bias, const float* __restrict__ logs,
    float* __restrict__ out) {
    __shared__ float As[16][132];
    __shared__ float Bs[16][132];
    __shared__ float partSq[128][17];
    __shared__ float rowH0[128];
    __shared__ float rowT[128];
    __shared__ float rowSc[128];

    int tid = threadIdx.x;
    int tx = tid & 15, ty = tid >> 4;
    int rowBase = blockIdx.x * 128;

    float acc[8][8];
#pragma unroll
    for (int i = 0; i < 8; i++)
#pragma unroll
        for (int j = 0; j < 8; j++) acc[i][j] = 0.f;

    int r  = tid >> 1;            // row/col index for loading (0..127)
    int kh = (tid & 1) * 8;       // k sub-offset (0 or 8)
    int grow = rowBase + r;

    for (int k0 = 0; k0 < DD; k0 += 16) {
        float4 xa, xb;
        if (grow < NN) {
            const float* p = X + (size_t)grow * DD + k0 + kh;
            xa = *(const float4*)p; xb = *(const float4*)(p + 4);
        } else {
            xa = make_float4(0.f, 0.f, 0.f, 0.f); xb = xa;
        }
        const float* q = W + (size_t)r * DD + k0 + kh;
        float4 wa = *(const float4*)q; float4 wb = *(const float4*)(q + 4);

        As[kh + 0][r] = xa.x; As[kh + 1][r] = xa.y; As[kh + 2][r] = xa.z; As[kh + 3][r] = xa.w;
        As[kh + 4][r] = xb.x; As[kh + 5][r] = xb.y; As[kh + 6][r] = xb.z; As[kh + 7][r] = xb.w;
        Bs[kh + 0][r] = wa.x; Bs[kh + 1][r] = wa.y; Bs[kh + 2][r] = wa.z; Bs[kh + 3][r] = wa.w;
        Bs[kh + 4][r] = wb.x; Bs[kh + 5][r] = wb.y; Bs[kh + 6][r] = wb.z; Bs[kh + 7][r] = wb.w;
        __syncthreads();

#pragma unroll
        for (int k = 0; k < 16; k++) {
            float a[8], b[8];
#pragma unroll
            for (int i = 0; i < 8; i++) a[i] = As[k][ty * 8 + i];
#pragma unroll
            for (int j = 0; j < 8; j++) b[j] = Bs[k][tx * 8 + j];
#pragma unroll
            for (int i = 0; i < 8; i++)
#pragma unroll
                for (int j = 0; j < 8; j++) acc[i][j] += a[i] * b[j];
        }
        __syncthreads();
    }

    float sEff = fminf(expf(logs[0]), 10.0f);
    float bj[8];
#pragma unroll
    for (int j = 0; j < 8; j++) bj[j] = bias[tx * 8 + j];

#pragma unroll
    for (int i = 0; i < 8; i++) {
        float ps = 0.f;
#pragma unroll
        for (int j = 0; j < 8; j++) {
            float c = acc[i][j] + bj[j];
            acc[i][j] = c;
            if (!(tx == 0 && j == 0)) ps += c * c;  // exclude time column
        }
        partSq[ty * 8 + i][tx] = ps;
        if (tx == 0) rowH0[ty * 8 + i] = acc[i][0];
    }
    __syncthreads();

    if (tid < 128) {
        float sq = 0.f;
#pragma unroll
        for (int t = 0; t < 16; t++) sq += partSq[tid][t];
        sq = fmaxf(sq, EPSV);
        float h0 = rowH0[tid];
        float tme = sEff / (1.f + expf(-h0)) + 1.5f;   // sigmoid*s + sqrt(C)+0.5
        float sc = (tme * tme - 1.0f) / sq;
        rowT[tid]  = tme;
        rowSc[tid] = sqrtf(fmaxf(sc, EPSV));
    }
    __syncthreads();

#pragma unroll
    for (int i = 0; i < 8; i++) {
        int rr = ty * 8 + i;
        int gr = rowBase + rr;
        if (gr >= NN) continue;
        float tme = rowT[rr], sc = rowSc[rr];
        float4 o1, o2;
        o1.x = (tx == 0) ? tme : acc[i][0] * sc;
        o1.y = acc[i][1] * sc; o1.z = acc[i][2] * sc; o1.w = acc[i][3] * sc;
        o2.x = acc[i][4] * sc; o2.y = acc[i][5] * sc;
        o2.z = acc[i][6] * sc; o2.w = acc[i][7] * sc;
        float* op = out + (size_t)gr * DD + tx * 8;
        *(float4*)op       = o1;
        *(float4*)(op + 4) = o2;
    }
}

// ---------------------------------------------------------------------------
// Zero kernel for scatter target
// ---------------------------------------------------------------------------
__global__ void zero_kernel(float4* __restrict__ p) {
    int i = blockIdx.x * blockDim.x + threadIdx.x;
    if (i < NN * DD / 4) p[i] = make_float4(0.f, 0.f, 0.f, 0.f);
}

// ---------------------------------------------------------------------------
// Stage 3/5: weighted scatter-add over edges. One warp per edge (32 x float4).
// Vector reds (red.global.add.v4.f32) to quarter the L2 atomic op count.
// ---------------------------------------------------------------------------
__global__ void agg_kernel(const float* __restrict__ Y, const float* __restrict__ ew,
                           const int* __restrict__ er, const int* __restrict__ ec,
                           float* __restrict__ S) {
    int lane = threadIdx.x & 31;
    int warp = (blockIdx.x * blockDim.x + threadIdx.x) >> 5;
    int nw   = (gridDim.x * blockDim.x) >> 5;
    for (int e = warp; e < EE; e += nw) {
        int col = ec[e];
        int row = er[e];
        float w = ew[e];
        float4 v = *(const float4*)(Y + (size_t)col * DD + lane * 4);
        v.x *= w; v.y *= w; v.z *= w; v.w *= w;
        float* dst = S + (size_t)row * DD + lane * 4;
        asm volatile("red.global.add.v4.f32 [%0], {%1,%2,%3,%4};"
                     :: "l"(dst), "f"(v.x), "f"(v.y), "f"(v.z), "f"(v.w)
                     : "memory");
    }
}

// ---------------------------------------------------------------------------
// Normalize (lorentz_agg denominator), optional fused relu for the next layer.
// ---------------------------------------------------------------------------
__global__ void norm_kernel(const float* __restrict__ S, float* __restrict__ out, int relu) {
    int lane = threadIdx.x & 31;
    int warp = (blockIdx.x * blockDim.x + threadIdx.x) >> 5;
    if (warp >= NN) return;
    float4 v = *(const float4*)(S + (size_t)warp * DD + lane * 4);
    float ss = v.x * v.x + v.y * v.y + v.z * v.z + v.w * v.w;
    ss = warpSum(ss);
    float s0 = __shfl_sync(0xffffffffu, v.x, 0);
    float neg = 2.f * s0 * s0 - ss;   // s0^2 - (ss - s0^2)
    float inv = rsqrtf(fmaxf(fabsf(neg), EPSV));
    v.x *= inv; v.y *= inv; v.z *= inv; v.w *= inv;
    if (relu) {
        v.x = fmaxf(v.x, 0.f); v.y = fmaxf(v.y, 0.f);
        v.z = fmaxf(v.z, 0.f); v.w = fmaxf(v.w, 0.f);
    }
    *(float4*)(out + (size_t)warp * DD + lane * 4) = v;
}

// ---------------------------------------------------------------------------
// Final: normalize + signed inner product with class embeddings -> logits.
// One warp per node; cls (40x128) staged in smem.
// ---------------------------------------------------------------------------
__global__ void classify_kernel(const float* __restrict__ S, const float* __restrict__ cls,
                                const float* __restrict__ cbias, float* __restrict__ out) {
    __shared__ float clsS[NCLS * DD];
    __shared__ float cbS[NCLS];
    for (int i = threadIdx.x; i < NCLS * DD; i += blockDim.x) clsS[i] = cls[i];
    if (threadIdx.x < NCLS) cbS[threadIdx.x] = cbias[threadIdx.x];
    __syncthreads();

    int lane = threadIdx.x & 31;
    int warp = (blockIdx.x * blockDim.x + threadIdx.x) >> 5;
    if (warp >= NN) return;

    float4 v = *(const float4*)(S + (size_t)warp * DD + lane * 4);
    float ss = v.x * v.x + v.y * v.y + v.z * v.z + v.w * v.w;
    ss = warpSum(ss);
    float s0 = __shfl_sync(0xffffffffu, v.x, 0);
    float neg = 2.f * s0 * s0 - ss;
    float inv2 = 2.f * rsqrtf(fmaxf(fabsf(neg), EPSV));

#pragma unroll 4
    for (int c = 0; c < NCLS; c++) {
        const float4 w = *(const float4*)(clsS + c * DD + lane * 4);
        float d = v.x * w.x + v.y * w.y + v.z * w.z + v.w * w.w;
        d = warpSum(d);
        if (lane == 0)
            out[(size_t)warp * NCLS + c] = 2.0f + inv2 * (d - 2.f * s0 * w.x) + cbS[c];
    }
}

// ---------------------------------------------------------------------------
extern "C" void kernel_launch(void* const* d_in, const int* in_sizes, int n_in,
                              void* d_out, int out_size) {
    const float* node_feat = (const float*)d_in[0];
    const float* W1   = (const float*)d_in[1];
    const float* b1   = (const float*)d_in[2];
    const float* s1   = (const float*)d_in[3];
    const float* W2   = (const float*)d_in[4];
    const float* b2   = (const float*)d_in[5];
    const float* s2   = (const float*)d_in[6];
    const float* cls  = (const float*)d_in[7];
    const float* cbias= (const float*)d_in[8];
    const float* ew   = (const float*)d_in[9];
    const int*   er   = (const int*)d_in[10];
    const int*   ec   = (const int*)d_in[11];
    float* out = (float*)d_out;

    float *A, *B, *S;
    cudaGetSymbolAddress((void**)&A, g_A);
    cudaGetSymbolAddress((void**)&B, g_B);
    cudaGetSymbolAddress((void**)&S, g_S);

    const int WARPS_BLOCKS = (NN + 7) / 8;           // 6250 (8 warps/block)
    const int GEMM_BLOCKS  = (NN + 127) / 128;       // 391
    const int ZERO_BLOCKS  = (NN * DD / 4 + 255) / 256; // 6250

    // x = expmap0(node_feat)
    expmap_kernel<<<WARPS_BLOCKS, 256>>>(node_feat, A);
    // x = lorentz_linear(x, W1, b1, s1, nonlin=False)
    gemm_lorentz<<<GEMM_BLOCKS, 256>>>(A, W1, b1, s1, B);
    // x = lorentz_agg(x, ...)
    zero_kernel<<<ZERO_BLOCKS, 256>>>((float4*)S);
    agg_kernel<<<4096, 256>>>(B, ew, er, ec, S);
    norm_kernel<<<WARPS_BLOCKS, 256>>>(S, A, 1);  // fused relu for next layer
    // x = lorentz_linear(relu(x), W2, b2, s2)
    gemm_lorentz<<<GEMM_BLOCKS, 256>>>(A, W2, b2, s2, B);
    // x = lorentz_agg(x, ...)
    zero_kernel<<<ZERO_BLOCKS, 256>>>((float4*)S);
    agg_kernel<<<4096, 256>>>(B, ew, er, ec, S);
    // logits
    classify_kernel<<<WARPS_BLOCKS, 256>>>(S, cls, cbias, out);
}

// round 2
// speedup vs baseline: 1.0097x; 1.0097x over previous
#include <cuda_runtime.h>
#include <math.h>

#define NN   50000
#define EE   800000
#define DIN  127
#define DD   128
#define NCLS 40
#define EPSV 1e-8f

// Scratch (__device__ globals: allocation-free rule)
__device__ float g_A[NN * DD];
__device__ float g_B[NN * DD];
__device__ int   g_deg[NN];
__device__ int   g_offs[NN];
__device__ int   g_cursor[NN];
__device__ int   g_bcol[EE];
__device__ float g_bw[EE];

__device__ __forceinline__ float warpSum(float v) {
#pragma unroll
    for (int o = 16; o; o >>= 1) v += __shfl_xor_sync(0xffffffffu, v, o);
    return v;
}

// ---------------------------------------------------------------------------
// Edge binning: count -> scan -> scatter (done once; reused by both aggs)
// ---------------------------------------------------------------------------
__global__ void zero_deg_kernel(int* __restrict__ deg) {
    int i = blockIdx.x * blockDim.x + threadIdx.x;
    if (i < NN) deg[i] = 0;
}

__global__ void count_kernel(const int* __restrict__ er, int* __restrict__ deg) {
    int i = blockIdx.x * blockDim.x + threadIdx.x;
    int stride = gridDim.x * blockDim.x;
    for (int e = i; e < EE; e += stride) atomicAdd(&deg[er[e]], 1);
}

// Single-block exclusive scan over 50000 counts (1024 threads, 49 elems each)
__global__ void scan_kernel(const int* __restrict__ deg, int* __restrict__ offs,
                            int* __restrict__ cursor) {
    __shared__ int sums[1024];
    const int CH = (NN + 1023) / 1024;   // 49
    int t = threadIdx.x;
    int base = t * CH;
    int s = 0;
    for (int i = 0; i < CH; i++) {
        int idx = base + i;
        if (idx < NN) s += deg[idx];
    }
    sums[t] = s;
    __syncthreads();
    // Blelloch-free simple scan (1024 elems, log steps via smem)
    for (int o = 1; o < 1024; o <<= 1) {
        int v = (t >= o) ? sums[t - o] : 0;
        __syncthreads();
        sums[t] += v;
        __syncthreads();
    }
    int run = (t == 0) ? 0 : sums[t - 1];   // exclusive prefix
    for (int i = 0; i < CH; i++) {
        int idx = base + i;
        if (idx < NN) {
            offs[idx] = run;
            cursor[idx] = run;
            run += deg[idx];
        }
    }
}

__global__ void scatter_kernel(const int* __restrict__ er, const int* __restrict__ ec,
                               const float* __restrict__ ew,
                               int* __restrict__ cursor,
                               int* __restrict__ bcol, float* __restrict__ bw) {
    int i = blockIdx.x * blockDim.x + threadIdx.x;
    int stride = gridDim.x * blockDim.x;
    for (int e = i; e < EE; e += stride) {
        int r = er[e];
        int pos = atomicAdd(&cursor[r], 1);
        bcol[pos] = ec[e];
        bw[pos]   = ew[e];
    }
}

// ---------------------------------------------------------------------------
// Stage 1: expmap0. One warp per node.
// ---------------------------------------------------------------------------
__global__ void expmap_kernel(const float* __restrict__ nf, float* __restrict__ out) {
    int lane = threadIdx.x & 31;
    int warp = (blockIdx.x * blockDim.x + threadIdx.x) >> 5;
    if (warp >= NN) return;
    const float* u = nf + (size_t)warp * DIN;
    float v[4];
    float ss = 0.f;
#pragma unroll
    for (int i = 0; i < 4; i++) {
        int j = lane * 4 + i;
        v[i] = (j < DIN) ? u[j] : 0.f;
        ss += v[i] * v[i];
    }
    ss = warpSum(ss);
    float nrm = fmaxf(sqrtf(ss), EPSV);
    float f = sinhf(nrm) / nrm;
    float* o = out + (size_t)warp * DD;
    if (lane == 0) o[0] = coshf(nrm);
#pragma unroll
    for (int i = 0; i < 4; i++) {
        int j = lane * 4 + i;
        if (j < DIN) o[1 + j] = f * v[i];
    }
}

// ---------------------------------------------------------------------------
// GEMM: H = X @ W^T + b with Lorentz epilogue. BM=128,BN=128,BK=16, 8x8 micro.
// ---------------------------------------------------------------------------
__global__ __launch_bounds__(256) void gemm_lorentz(
    const float* __restrict__ X, const float* __restrict__ W,
    const float* __restrict__ bias, const float* __restrict__ logs,
    float* __restrict__ out) {
    __shared__ float As[16][132];
    __shared__ float Bs[16][132];
    __shared__ float partSq[128][17];
    __shared__ float rowH0[128];
    __shared__ float rowT[128];
    __shared__ float rowSc[128];

    int tid = threadIdx.x;
    int tx = tid & 15, ty = tid >> 4;
    int rowBase = blockIdx.x * 128;

    float acc[8][8];
#pragma unroll
    for (int i = 0; i < 8; i++)
#pragma unroll
        for (int j = 0; j < 8; j++) acc[i][j] = 0.f;

    int r  = tid >> 1;
    int kh = (tid & 1) * 8;
    int grow = rowBase + r;

    for (int k0 = 0; k0 < DD; k0 += 16) {
        float4 xa, xb;
        if (grow < NN) {
            const float* p = X + (size_t)grow * DD + k0 + kh;
            xa = *(const float4*)p; xb = *(const float4*)(p + 4);
        } else {
            xa = make_float4(0.f, 0.f, 0.f, 0.f); xb = xa;
        }
        const float* q = W + (size_t)r * DD + k0 + kh;
        float4 wa = *(const float4*)q; float4 wb = *(const float4*)(q + 4);

        As[kh + 0][r] = xa.x; As[kh + 1][r] = xa.y; As[kh + 2][r] = xa.z; As[kh + 3][r] = xa.w;
        As[kh + 4][r] = xb.x; As[kh + 5][r] = xb.y; As[kh + 6][r] = xb.z; As[kh + 7][r] = xb.w;
        Bs[kh + 0][r] = wa.x; Bs[kh + 1][r] = wa.y; Bs[kh + 2][r] = wa.z; Bs[kh + 3][r] = wa.w;
        Bs[kh + 4][r] = wb.x; Bs[kh + 5][r] = wb.y; Bs[kh + 6][r] = wb.z; Bs[kh + 7][r] = wb.w;
        __syncthreads();

#pragma unroll
        for (int k = 0; k < 16; k++) {
            float a[8], b[8];
#pragma unroll
            for (int i = 0; i < 8; i++) a[i] = As[k][ty * 8 + i];
#pragma unroll
            for (int j = 0; j < 8; j++) b[j] = Bs[k][tx * 8 + j];
#pragma unroll
            for (int i = 0; i < 8; i++)
#pragma unroll
                for (int j = 0; j < 8; j++) acc[i][j] += a[i] * b[j];
        }
        __syncthreads();
    }

    float sEff = fminf(expf(logs[0]), 10.0f);
    float bj[8];
#pragma unroll
    for (int j = 0; j < 8; j++) bj[j] = bias[tx * 8 + j];

#pragma unroll
    for (int i = 0; i < 8; i++) {
        float ps = 0.f;
#pragma unroll
        for (int j = 0; j < 8; j++) {
            float c = acc[i][j] + bj[j];
            acc[i][j] = c;
            if (!(tx == 0 && j == 0)) ps += c * c;
        }
        partSq[ty * 8 + i][tx] = ps;
        if (tx == 0) rowH0[ty * 8 + i] = acc[i][0];
    }
    __syncthreads();

    if (tid < 128) {
        float sq = 0.f;
#pragma unroll
        for (int t = 0; t < 16; t++) sq += partSq[tid][t];
        sq = fmaxf(sq, EPSV);
        float h0 = rowH0[tid];
        float tme = sEff / (1.f + expf(-h0)) + 1.5f;
        float sc = (tme * tme - 1.0f) / sq;
        rowT[tid]  = tme;
        rowSc[tid] = sqrtf(fmaxf(sc, EPSV));
    }
    __syncthreads();

#pragma unroll
    for (int i = 0; i < 8; i++) {
        int rr = ty * 8 + i;
        int gr = rowBase + rr;
        if (gr >= NN) continue;
        float tme = rowT[rr], sc = rowSc[rr];
        float4 o1, o2;
        o1.x = (tx == 0) ? tme : acc[i][0] * sc;
        o1.y = acc[i][1] * sc; o1.z = acc[i][2] * sc; o1.w = acc[i][3] * sc;
        o2.x = acc[i][4] * sc; o2.y = acc[i][5] * sc;
        o2.z = acc[i][6] * sc; o2.w = acc[i][7] * sc;
        float* op = out + (size_t)gr * DD + tx * 8;
        *(float4*)op       = o1;
        *(float4*)(op + 4) = o2;
    }
}

// ---------------------------------------------------------------------------
// Gather-based aggregation: one warp per node, pure reads, fused epilogue.
// MODE 0: lorentz-agg normalize + relu -> out (node features)
// MODE 1: lorentz-agg normalize + class logits -> out (N x NCLS)
// ---------------------------------------------------------------------------
template<int MODE>
__global__ __launch_bounds__(256) void agg_gather(
    const float* __restrict__ Y,
    const int* __restrict__ offs, const int* __restrict__ deg,
    const int* __restrict__ bcol, const float* __restrict__ bw,
    const float* __restrict__ cls, const float* __restrict__ cbias,
    float* __restrict__ out) {

    __shared__ float clsS[MODE ? NCLS * DD : 1];
    __shared__ float cbS[MODE ? NCLS : 1];
    if (MODE) {
        for (int i = threadIdx.x; i < NCLS * DD; i += blockDim.x) clsS[i] = cls[i];
        if (threadIdx.x < NCLS) cbS[threadIdx.x] = cbias[threadIdx.x];
        __syncthreads();
    }

    int lane = threadIdx.x & 31;
    int node = (blockIdx.x * blockDim.x + threadIdx.x) >> 5;
    if (node >= NN) return;

    int s = offs[node];
    int n = deg[node];
    float4 acc = make_float4(0.f, 0.f, 0.f, 0.f);

    int j = s;
    // unroll by 2 for load-level parallelism
    for (; j + 1 < s + n; j += 2) {
        int   c0 = bcol[j],     c1 = bcol[j + 1];
        float w0 = bw[j],       w1 = bw[j + 1];
        float4 v0 = *(const float4*)(Y + (size_t)c0 * DD + lane * 4);
        float4 v1 = *(const float4*)(Y + (size_t)c1 * DD + lane * 4);
        acc.x += w0 * v0.x + w1 * v1.x;
        acc.y += w0 * v0.y + w1 * v1.y;
        acc.z += w0 * v0.z + w1 * v1.z;
        acc.w += w0 * v0.w + w1 * v1.w;
    }
    if (j < s + n) {
        int c0 = bcol[j]; float w0 = bw[j];
        float4 v0 = *(const float4*)(Y + (size_t)c0 * DD + lane * 4);
        acc.x += w0 * v0.x; acc.y += w0 * v0.y;
        acc.z += w0 * v0.z; acc.w += w0 * v0.w;
    }

    // Lorentz-agg normalization
    float ss = acc.x * acc.x + acc.y * acc.y + acc.z * acc.z + acc.w * acc.w;
    ss = warpSum(ss);
    float s0 = __shfl_sync(0xffffffffu, acc.x, 0);
    float neg = 2.f * s0 * s0 - ss;          // time^2 - space^2
    float inv = rsqrtf(fmaxf(fabsf(neg), EPSV));

    if (MODE == 0) {
        float4 v;
        v.x = fmaxf(acc.x * inv, 0.f);
        v.y = fmaxf(acc.y * inv, 0.f);
        v.z = fmaxf(acc.z * inv, 0.f);
        v.w = fmaxf(acc.w * inv, 0.f);
        if (lane == 0) v.x = acc.x * inv;    // time coord: no relu? relu applies to all
        // NOTE: reference applies relu to ALL coords including time.
        v.x = fmaxf(acc.x * inv, 0.f);
        *(float4*)(out + (size_t)node * DD + lane * 4) = v;
    } else {
        float x0 = s0 * inv;                 // normalized time coord
        float4 v;
        v.x = acc.x * inv; v.y = acc.y * inv; v.z = acc.z * inv; v.w = acc.w * inv;
#pragma unroll 4
        for (int c = 0; c < NCLS; c++) {
            const float4 w = *(const float4*)(clsS + c * DD + lane * 4);
            float d = v.x * w.x + v.y * w.y + v.z * w.z + v.w * w.w;
            d = warpSum(d);
            if (lane == 0) {
                float w0 = clsS[c * DD];     // class time coord
                out[(size_t)node * NCLS + c] = 2.0f + 2.0f * (d - 2.f * x0 * w0) + cbS[c];
            }
        }
    }
}

// ---------------------------------------------------------------------------
extern "C" void kernel_launch(void* const* d_in, const int* in_sizes, int n_in,
                              void* d_out, int out_size) {
    const float* node_feat = (const float*)d_in[0];
    const float* W1   = (const float*)d_in[1];
    const float* b1   = (const float*)d_in[2];
    const float* s1   = (const float*)d_in[3];
    const float* W2   = (const float*)d_in[4];
    const float* b2   = (const float*)d_in[5];
    const float* s2   = (const float*)d_in[6];
    const float* cls  = (const float*)d_in[7];
    const float* cbias= (const float*)d_in[8];
    const float* ew   = (const float*)d_in[9];
    const int*   er   = (const int*)d_in[10];
    const int*   ec   = (const int*)d_in[11];
    float* out = (float*)d_out;

    float *A, *B, *bwv;
    int *deg, *offs, *cursor, *bcol;
    cudaGetSymbolAddress((void**)&A, g_A);
    cudaGetSymbolAddress((void**)&B, g_B);
    cudaGetSymbolAddress((void**)&deg, g_deg);
    cudaGetSymbolAddress((void**)&offs, g_offs);
    cudaGetSymbolAddress((void**)&cursor, g_cursor);
    cudaGetSymbolAddress((void**)&bcol, g_bcol);
    cudaGetSymbolAddress((void**)&bwv, g_bw);

    const int WARPS_BLOCKS = (NN + 7) / 8;      // 6250
    const int GEMM_BLOCKS  = (NN + 127) / 128;  // 391

    // Edge binning (shared by both aggregations)
    zero_deg_kernel<<<(NN + 255) / 256, 256>>>(deg);
    count_kernel<<<1024, 256>>>(er, deg);
    scan_kernel<<<1, 1024>>>(deg, offs, cursor);
    scatter_kernel<<<1024, 256>>>(er, ec, ew, cursor, bcol, bwv);

    // Pipeline
    expmap_kernel<<<WARPS_BLOCKS, 256>>>(node_feat, A);
    gemm_lorentz<<<GEMM_BLOCKS, 256>>>(A, W1, b1, s1, B);
    agg_gather<0><<<WARPS_BLOCKS, 256>>>(B, offs, deg, bcol, bwv,
                                         nullptr, nullptr, A);
    gemm_lorentz<<<GEMM_BLOCKS, 256>>>(A, W2, b2, s2, B);
    agg_gather<1><<<WARPS_BLOCKS, 256>>>(B, offs, deg, bcol, bwv,
                                         cls, cbias, out);
}

// round 3
// speedup vs baseline: 1.0440x; 1.0340x over previous
#include <cuda_runtime.h>
#include <math.h>

#define NN   50000
#define EE   800000
#define DIN  127
#define DD   128
#define NCLS 40
#define EPSV 1e-8f

#define GBM  64      // gemm block rows
#define LDP  68      // smem panel leading dim (floats): 4g+t conflict-free
#define LDD  132     // D staging leading dim

// Scratch (__device__ globals: allocation-free rule)
__device__ float g_A[NN * DD];
__device__ float g_B[NN * DD];
__device__ int   g_deg[NN];
__device__ int   g_offs[NN];
__device__ int   g_cursor[NN];
__device__ int2  g_pair[EE];

__device__ __forceinline__ float warpSum(float v) {
#pragma unroll
    for (int o = 16; o; o >>= 1) v += __shfl_xor_sync(0xffffffffu, v, o);
    return v;
}

__device__ __forceinline__ void split_tf32(float x, unsigned& hi, unsigned& lo) {
    unsigned h;
    asm("cvt.rna.tf32.f32 %0, %1;" : "=r"(h) : "f"(x));
    float r = x - __uint_as_float(h);
    unsigned l;
    asm("cvt.rna.tf32.f32 %0, %1;" : "=r"(l) : "f"(r));
    hi = h; lo = l;
}

__device__ __forceinline__ void mma8(float* d, const unsigned* a, const unsigned* b) {
    asm volatile(
        "mma.sync.aligned.m16n8k8.row.col.f32.tf32.tf32.f32 "
        "{%0,%1,%2,%3}, {%4,%5,%6,%7}, {%8,%9}, {%0,%1,%2,%3};"
        : "+f"(d[0]), "+f"(d[1]), "+f"(d[2]), "+f"(d[3])
        : "r"(a[0]), "r"(a[1]), "r"(a[2]), "r"(a[3]), "r"(b[0]), "r"(b[1]));
}

// ---------------------------------------------------------------------------
// Edge binning
// ---------------------------------------------------------------------------
__global__ void zero_deg_kernel(int* __restrict__ deg) {
    int i = blockIdx.x * blockDim.x + threadIdx.x;
    if (i < NN) deg[i] = 0;
}

__global__ void count_kernel(const int* __restrict__ er, int* __restrict__ deg) {
    int i = blockIdx.x * blockDim.x + threadIdx.x;
    int stride = gridDim.x * blockDim.x;
    for (int e = i; e < EE; e += stride) atomicAdd(&deg[er[e]], 1);
}

__global__ void scan_kernel(const int* __restrict__ deg, int* __restrict__ offs,
                            int* __restrict__ cursor) {
    __shared__ int sums[1024];
    const int CH = (NN + 1023) / 1024;
    int t = threadIdx.x;
    int base = t * CH;
    int s = 0;
    for (int i = 0; i < CH; i++) {
        int idx = base + i;
        if (idx < NN) s += deg[idx];
    }
    sums[t] = s;
    __syncthreads();
    for (int o = 1; o < 1024; o <<= 1) {
        int v = (t >= o) ? sums[t - o] : 0;
        __syncthreads();
        sums[t] += v;
        __syncthreads();
    }
    int run = (t == 0) ? 0 : sums[t - 1];
    for (int i = 0; i < CH; i++) {
        int idx = base + i;
        if (idx < NN) {
            offs[idx] = run;
            cursor[idx] = run;
            run += deg[idx];
        }
    }
}

__global__ void scatter_kernel(const int* __restrict__ er, const int* __restrict__ ec,
                               const float* __restrict__ ew,
                               int* __restrict__ cursor, int2* __restrict__ pair) {
    int i = blockIdx.x * blockDim.x + threadIdx.x;
    int stride = gridDim.x * blockDim.x;
    for (int e = i; e < EE; e += stride) {
        int r = er[e];
        int pos = atomicAdd(&cursor[r], 1);
        pair[pos] = make_int2(ec[e], __float_as_int(ew[e]));
    }
}

// ---------------------------------------------------------------------------
// expmap0: one warp per node
// ---------------------------------------------------------------------------
__global__ void expmap_kernel(const float* __restrict__ nf, float* __restrict__ out) {
    int lane = threadIdx.x & 31;
    int warp = (blockIdx.x * blockDim.x + threadIdx.x) >> 5;
    if (warp >= NN) return;
    const float* u = nf + (size_t)warp * DIN;
    float v[4];
    float ss = 0.f;
#pragma unroll
    for (int i = 0; i < 4; i++) {
        int j = lane * 4 + i;
        v[i] = (j < DIN) ? u[j] : 0.f;
        ss += v[i] * v[i];
    }
    ss = warpSum(ss);
    float nrm = fmaxf(sqrtf(ss), EPSV);
    float f = sinhf(nrm) / nrm;
    float* o = out + (size_t)warp * DD;
    if (lane == 0) o[0] = coshf(nrm);
#pragma unroll
    for (int i = 0; i < 4; i++) {
        int j = lane * 4 + i;
        if (j < DIN) o[1 + j] = f * v[i];
    }
}

// ---------------------------------------------------------------------------
// GEMM via 3xTF32 mma.sync: H = X @ W^T + b, Lorentz epilogue.
// Block: 64 rows x 128 cols. 8 warps: warpM in {0,1} (32 rows), warpN in
// {0..3} (32 cols). Warp tile 32x32 -> mf 2 x nf 4 m16n8k8 fragments.
// ---------------------------------------------------------------------------
__global__ void __launch_bounds__(256, 2) gemm_tc(
    const float* __restrict__ X, const float* __restrict__ W,
    const float* __restrict__ bias, const float* __restrict__ logs,
    float* __restrict__ out) {
    extern __shared__ float sm[];
    float* sX = sm;                         // 64*68 = 4352 floats
    float* sW = sm + GBM * LDP;             // 128*68 = 8704 floats
    float* sD = sm;                         // reuse (8448 floats)
    float* rowT = sm + GBM * LDP + 128 * LDP;   // 64
    float* rowS = rowT + GBM;                   // 64

    int tid = threadIdx.x;
    int lane = tid & 31, wid = tid >> 5;
    int g = lane >> 2, t = lane & 3;
    int warpM = wid & 1, warpN = wid >> 1;
    int rowBase = blockIdx.x * GBM;

    float acc[2][4][4];
#pragma unroll
    for (int a = 0; a < 2; a++)
#pragma unroll
        for (int b = 0; b < 4; b++)
#pragma unroll
            for (int c = 0; c < 4; c++) acc[a][b][c] = 0.f;

    for (int kb = 0; kb < DD; kb += 64) {
        // Load X panel (64 x 64) -> 1024 float4, 4 per thread
#pragma unroll
        for (int i = 0; i < 4; i++) {
            int idx = tid + 256 * i;
            int r = idx >> 4, c4 = idx & 15;
            int gr = rowBase + r;
            float4 v = make_float4(0.f, 0.f, 0.f, 0.f);
            if (gr < NN) v = *(const float4*)(X + (size_t)gr * DD + kb + c4 * 4);
            *(float4*)(sX + r * LDP + c4 * 4) = v;
        }
        // Load W panel (128 x 64) -> 2048 float4, 8 per thread
#pragma unroll
        for (int i = 0; i < 8; i++) {
            int idx = tid + 256 * i;
            int r = idx >> 4, c4 = idx & 15;
            float4 v = *(const float4*)(W + (size_t)r * DD + kb + c4 * 4);
            *(float4*)(sW + r * LDP + c4 * 4) = v;
        }
        __syncthreads();

#pragma unroll
        for (int ks = 0; ks < 8; ks++) {
            int k0 = ks * 8;
            unsigned ah[2][4], al[2][4], bh[4][2], bl[4][2];
#pragma unroll
            for (int mf = 0; mf < 2; mf++) {
                int r0 = warpM * 32 + mf * 16 + g;
                split_tf32(sX[r0 * LDP + k0 + t],           ah[mf][0], al[mf][0]);
                split_tf32(sX[(r0 + 8) * LDP + k0 + t],     ah[mf][1], al[mf][1]);
                split_tf32(sX[r0 * LDP + k0 + t + 4],       ah[mf][2], al[mf][2]);
                split_tf32(sX[(r0 + 8) * LDP + k0 + t + 4], ah[mf][3], al[mf][3]);
            }
#pragma unroll
            for (int nf = 0; nf < 4; nf++) {
                int c0 = warpN * 32 + nf * 8 + g;
                split_tf32(sW[c0 * LDP + k0 + t],     bh[nf][0], bl[nf][0]);
                split_tf32(sW[c0 * LDP + k0 + t + 4], bh[nf][1], bl[nf][1]);
            }
#pragma unroll
            for (int mf = 0; mf < 2; mf++)
#pragma unroll
                for (int nf = 0; nf < 4; nf++) {
                    mma8(acc[mf][nf], al[mf], bh[nf]);
                    mma8(acc[mf][nf], ah[mf], bl[nf]);
                    mma8(acc[mf][nf], ah[mf], bh[nf]);
                }
        }
        __syncthreads();
    }

    // Stage D (+bias) into smem
#pragma unroll
    for (int mf = 0; mf < 2; mf++)
#pragma unroll
        for (int nf = 0; nf < 4; nf++) {
            int r0 = warpM * 32 + mf * 16 + g;
            int c0 = warpN * 32 + nf * 8 + 2 * t;
            float b0 = __ldg(bias + c0), b1 = __ldg(bias + c0 + 1);
            sD[r0 * LDD + c0]           = acc[mf][nf][0] + b0;
            sD[r0 * LDD + c0 + 1]       = acc[mf][nf][1] + b1;
            sD[(r0 + 8) * LDD + c0]     = acc[mf][nf][2] + b0;
            sD[(r0 + 8) * LDD + c0 + 1] = acc[mf][nf][3] + b1;
        }
    __syncthreads();

    // Row stats: 4 threads per row, 32 cols each
    {
        int row = tid >> 2, q = tid & 3;
        const float* dr = sD + row * LDD + q * 32;
        float sq = 0.f, h0 = 0.f;
#pragma unroll
        for (int c = 0; c < 32; c++) { float v = dr[c]; sq += v * v; }
        if (q == 0) { h0 = dr[0]; sq -= h0 * h0; }
        sq += __shfl_xor_sync(0xffffffffu, sq, 1);
        sq += __shfl_xor_sync(0xffffffffu, sq, 2);
        if (q == 0) {
            float sEff = fminf(expf(logs[0]), 10.0f);
            sq = fmaxf(sq, EPSV);
            float tme = sEff / (1.f + expf(-h0)) + 1.5f;
            float sc = sqrtf(fmaxf((tme * tme - 1.0f) / sq, EPSV));
            rowT[row] = tme;
            rowS[row] = sc;
        }
    }
    __syncthreads();

    // Scale + write
    {
        int row = tid >> 2, q = tid & 3;
        int gr = rowBase + row;
        if (gr < NN) {
            float tme = rowT[row], sc = rowS[row];
            const float* dr = sD + row * LDD + q * 32;
            float* op = out + (size_t)gr * DD + q * 32;
#pragma unroll
            for (int c4 = 0; c4 < 8; c4++) {
                float4 v = *(const float4*)(dr + c4 * 4);
                v.x *= sc; v.y *= sc; v.z *= sc; v.w *= sc;
                if (q == 0 && c4 == 0) v.x = tme;
                *(float4*)(op + c4 * 4) = v;
            }
        }
    }
}

// ---------------------------------------------------------------------------
// Gather aggregation, one warp per node, fused epilogues.
// MODE 0: normalize + relu -> features. MODE 1: normalize + logits.
// ---------------------------------------------------------------------------
template<int MODE>
__global__ __launch_bounds__(256) void agg_gather(
    const float* __restrict__ Y,
    const int* __restrict__ offs, const int* __restrict__ deg,
    const int2* __restrict__ pair,
    const float* __restrict__ cls, const float* __restrict__ cbias,
    float* __restrict__ out) {

    __shared__ float clsS[MODE ? NCLS * DD : 1];
    __shared__ float cbS[MODE ? NCLS : 1];
    if (MODE) {
        for (int i = threadIdx.x; i < NCLS * DD; i += blockDim.x) clsS[i] = cls[i];
        if (threadIdx.x < NCLS) cbS[threadIdx.x] = cbias[threadIdx.x];
        __syncthreads();
    }

    int lane = threadIdx.x & 31;
    int node = (blockIdx.x * blockDim.x + threadIdx.x) >> 5;
    if (node >= NN) return;

    int s = offs[node];
    int e = s + deg[node];
    const float4* Yv = (const float4*)Y;
    float4 acc = make_float4(0.f, 0.f, 0.f, 0.f);

    int j = s;
    for (; j + 4 <= e; j += 4) {
        int2 p0 = pair[j], p1 = pair[j + 1], p2 = pair[j + 2], p3 = pair[j + 3];
        float4 v0 = __ldcg(Yv + p0.x * 32 + lane);
        float4 v1 = __ldcg(Yv + p1.x * 32 + lane);
        float4 v2 = __ldcg(Yv + p2.x * 32 + lane);
        float4 v3 = __ldcg(Yv + p3.x * 32 + lane);
        float w0 = __int_as_float(p0.y), w1 = __int_as_float(p1.y);
        float w2 = __int_as_float(p2.y), w3 = __int_as_float(p3.y);
        acc.x += w0 * v0.x + w1 * v1.x + w2 * v2.x + w3 * v3.x;
        acc.y += w0 * v0.y + w1 * v1.y + w2 * v2.y + w3 * v3.y;
        acc.z += w0 * v0.z + w1 * v1.z + w2 * v2.z + w3 * v3.z;
        acc.w += w0 * v0.w + w1 * v1.w + w2 * v2.w + w3 * v3.w;
    }
    for (; j < e; j++) {
        int2 p = pair[j];
        float w = __int_as_float(p.y);
        float4 v = __ldcg(Yv + p.x * 32 + lane);
        acc.x += w * v.x; acc.y += w * v.y; acc.z += w * v.z; acc.w += w * v.w;
    }

    float ss = acc.x * acc.x + acc.y * acc.y + acc.z * acc.z + acc.w * acc.w;
    ss = warpSum(ss);
    float s0 = __shfl_sync(0xffffffffu, acc.x, 0);
    float neg = 2.f * s0 * s0 - ss;
    float inv = rsqrtf(fmaxf(fabsf(neg), EPSV));

    if (MODE == 0) {
        float4 v;
        v.x = fmaxf(acc.x * inv, 0.f);
        v.y = fmaxf(acc.y * inv, 0.f);
        v.z = fmaxf(acc.z * inv, 0.f);
        v.w = fmaxf(acc.w * inv, 0.f);
        *(float4*)(out + (size_t)node * DD + lane * 4) = v;
    } else {
        float x0 = s0 * inv;
        float4 v;
        v.x = acc.x * inv; v.y = acc.y * inv; v.z = acc.z * inv; v.w = acc.w * inv;
#pragma unroll 4
        for (int c = 0; c < NCLS; c++) {
            const float4 w = *(const float4*)(clsS + c * DD + lane * 4);
            float d = v.x * w.x + v.y * w.y + v.z * w.z + v.w * w.w;
            d = warpSum(d);
            if (lane == 0) {
                float w0 = clsS[c * DD];
                out[(size_t)node * NCLS + c] = 2.0f + 2.0f * (d - 2.f * x0 * w0) + cbS[c];
            }
        }
    }
}

// ---------------------------------------------------------------------------
extern "C" void kernel_launch(void* const* d_in, const int* in_sizes, int n_in,
                              void* d_out, int out_size) {
    const float* node_feat = (const float*)d_in[0];
    const float* W1   = (const float*)d_in[1];
    const float* b1   = (const float*)d_in[2];
    const float* s1   = (const float*)d_in[3];
    const float* W2   = (const float*)d_in[4];
    const float* b2   = (const float*)d_in[5];
    const float* s2   = (const float*)d_in[6];
    const float* cls  = (const float*)d_in[7];
    const float* cbias= (const float*)d_in[8];
    const float* ew   = (const float*)d_in[9];
    const int*   er   = (const int*)d_in[10];
    const int*   ec   = (const int*)d_in[11];
    float* out = (float*)d_out;

    float *A, *B;
    int *deg, *offs, *cursor;
    int2 *pair;
    cudaGetSymbolAddress((void**)&A, g_A);
    cudaGetSymbolAddress((void**)&B, g_B);
    cudaGetSymbolAddress((void**)&deg, g_deg);
    cudaGetSymbolAddress((void**)&offs, g_offs);
    cudaGetSymbolAddress((void**)&cursor, g_cursor);
    cudaGetSymbolAddress((void**)&pair, g_pair);

    const int WARPS_BLOCKS = (NN + 7) / 8;        // 6250
    const int GEMM_BLOCKS  = (NN + GBM - 1) / GBM; // 782
    const int GEMM_SMEM = (GBM * LDP + 128 * LDP + 2 * GBM) * 4; // 52736 B

    cudaFuncSetAttribute(gemm_tc, cudaFuncAttributeMaxDynamicSharedMemorySize,
                         GEMM_SMEM);

    // Edge binning (shared by both aggregations)
    zero_deg_kernel<<<(NN + 255) / 256, 256>>>(deg);
    count_kernel<<<1024, 256>>>(er, deg);
    scan_kernel<<<1, 1024>>>(deg, offs, cursor);
    scatter_kernel<<<1024, 256>>>(er, ec, ew, cursor, pair);

    // Pipeline
    expmap_kernel<<<WARPS_BLOCKS, 256>>>(node_feat, A);
    gemm_tc<<<GEMM_BLOCKS, 256, GEMM_SMEM>>>(A, W1, b1, s1, B);
    agg_gather<0><<<WARPS_BLOCKS, 256>>>(B, offs, deg, pair, nullptr, nullptr, A);
    gemm_tc<<<GEMM_BLOCKS, 256, GEMM_SMEM>>>(A, W2, b2, s2, B);
    agg_gather<1><<<WARPS_BLOCKS, 256>>>(B, offs, deg, pair, cls, cbias, out);
}